// round 4
// baseline (speedup 1.0000x reference)
#include <cuda_runtime.h>
#include <math.h>
#include <stdint.h>

#define MROWS 65536          // 4*128*128
#define CIN   180
#define CC2   360
#define NDTOT 3932160        // N*D, identical for all 3 paths (4*128*128*60)

// ---------------- scratch (static device globals; no runtime allocation) ----
__device__ float g_X1[(size_t)MROWS * CC2];     // conv1 output (94 MB)
__device__ float g_Q[NDTOT];
__device__ float g_V[NDTOT];
__device__ float g_Yw[NDTOT];
__device__ float g_Ycat[(size_t)MROWS * CIN];   // 47 MB
__device__ float g_part[4194304];               // split-K partials (16 MB)
__device__ float g_psum[256 * CC2];
__device__ float g_psq[256 * CC2];
__device__ float g_scale[CC2];
__device__ float g_shift[CC2];

// ====================== GEMM NN: C[M,N] = A[M,K]*B[K,N] (+bias[n]) ==========
// 128x128 block tile, BK=8, 256 threads, 8x8 per-thread microtile.
// Requires M % 128 == 0 (true for every call site). N,K arbitrary (guarded).
__global__ __launch_bounds__(256) void gemm_nn(
    const float* __restrict__ A, const float* __restrict__ B,
    float* __restrict__ C, int M, int N, int K, const float* __restrict__ bias)
{
    __shared__ float As[8][132];   // transposed A tile [k][m], pad 132 -> conflict-free
    __shared__ float Bs[8][128];   // B tile [k][n]
    const int tid  = threadIdx.x;
    const int row0 = blockIdx.y * 128;
    const int col0 = blockIdx.x * 128;
    const int lm   = tid >> 1;          // 0..127
    const int lk4  = (tid & 1) * 4;     // 0 or 4
    const int bk   = tid >> 5;          // 0..7
    const int bn4  = (tid & 31) * 4;    // 0..124
    const int ty   = tid >> 4, tx = tid & 15;

    float acc[8][8];
#pragma unroll
    for (int i = 0; i < 8; i++)
#pragma unroll
        for (int j = 0; j < 8; j++) acc[i][j] = 0.f;

    const float* Arow = A + (size_t)(row0 + lm) * K;

    for (int kk = 0; kk < K; kk += 8) {
        // ---- load A tile (128x8), store transposed
        float4 av;
        {
            int ka = kk + lk4;
            if (ka + 3 < K) {
                av = *reinterpret_cast<const float4*>(Arow + ka);
            } else {
                float t0 = (ka + 0 < K) ? Arow[ka + 0] : 0.f;
                float t1 = (ka + 1 < K) ? Arow[ka + 1] : 0.f;
                float t2 = (ka + 2 < K) ? Arow[ka + 2] : 0.f;
                float t3 = (ka + 3 < K) ? Arow[ka + 3] : 0.f;
                av = make_float4(t0, t1, t2, t3);
            }
        }
        As[lk4 + 0][lm] = av.x; As[lk4 + 1][lm] = av.y;
        As[lk4 + 2][lm] = av.z; As[lk4 + 3][lm] = av.w;
        // ---- load B tile (8x128)
        float4 bv = make_float4(0.f, 0.f, 0.f, 0.f);
        {
            int kb = kk + bk, cb = col0 + bn4;
            if (kb < K) {
                if (cb + 3 < N) {
                    bv = *reinterpret_cast<const float4*>(B + (size_t)kb * N + cb);
                } else {
                    const float* Bp = B + (size_t)kb * N;
                    if (cb + 0 < N) bv.x = Bp[cb + 0];
                    if (cb + 1 < N) bv.y = Bp[cb + 1];
                    if (cb + 2 < N) bv.z = Bp[cb + 2];
                    if (cb + 3 < N) bv.w = Bp[cb + 3];
                }
            }
        }
        *reinterpret_cast<float4*>(&Bs[bk][bn4]) = bv;
        __syncthreads();
#pragma unroll
        for (int k = 0; k < 8; k++) {
            const float4 a0 = *reinterpret_cast<const float4*>(&As[k][ty * 8]);
            const float4 a1 = *reinterpret_cast<const float4*>(&As[k][ty * 8 + 4]);
            const float4 b0 = *reinterpret_cast<const float4*>(&Bs[k][tx * 8]);
            const float4 b1 = *reinterpret_cast<const float4*>(&Bs[k][tx * 8 + 4]);
            float a[8] = {a0.x, a0.y, a0.z, a0.w, a1.x, a1.y, a1.z, a1.w};
            float b[8] = {b0.x, b0.y, b0.z, b0.w, b1.x, b1.y, b1.z, b1.w};
#pragma unroll
            for (int i = 0; i < 8; i++)
#pragma unroll
                for (int j = 0; j < 8; j++) acc[i][j] = fmaf(a[i], b[j], acc[i][j]);
        }
        __syncthreads();
    }

    const int crow = row0 + ty * 8;
    const int ccol = col0 + tx * 8;
    float bb[8];
#pragma unroll
    for (int j = 0; j < 8; j++)
        bb[j] = (bias != nullptr && ccol + j < N) ? bias[ccol + j] : 0.f;

    if (col0 + 128 <= N) {
#pragma unroll
        for (int i = 0; i < 8; i++) {
            float* Cp = C + (size_t)(crow + i) * N + ccol;
            float4 o0 = make_float4(acc[i][0] + bb[0], acc[i][1] + bb[1],
                                    acc[i][2] + bb[2], acc[i][3] + bb[3]);
            float4 o1 = make_float4(acc[i][4] + bb[4], acc[i][5] + bb[5],
                                    acc[i][6] + bb[6], acc[i][7] + bb[7]);
            *reinterpret_cast<float4*>(Cp)     = o0;
            *reinterpret_cast<float4*>(Cp + 4) = o1;
        }
    } else {
#pragma unroll
        for (int i = 0; i < 8; i++)
#pragma unroll
            for (int j = 0; j < 8; j++)
                if (ccol + j < N)
                    C[(size_t)(crow + i) * N + ccol + j] = acc[i][j] + bb[j];
    }
}

// ====================== GEMM NT: C[M,N] = A[M,K]*B[N,K]^T, optional split-K ==
// blockIdx.z = K-chunk index; chunk length Kc. If gridDim.z > 1, writes to
// C + z*M*N (partial buffer, reduced later). M,N % 128 == 0 at all call sites.
__global__ __launch_bounds__(256) void gemm_nt(
    const float* __restrict__ A, const float* __restrict__ B,
    float* __restrict__ C, int M, int N, int K, int Kc)
{
    __shared__ float As[8][132];
    __shared__ float Bs[8][132];
    const int tid  = threadIdx.x;
    const int row0 = blockIdx.y * 128;
    const int col0 = blockIdx.x * 128;
    const int zi   = blockIdx.z;
    const int kbase = zi * Kc;
    int kend = kbase + Kc; if (kend > K) kend = K;
    if (gridDim.z > 1) C += (size_t)zi * M * N;

    const int lm  = tid >> 1;
    const int lk4 = (tid & 1) * 4;
    const int ty  = tid >> 4, tx = tid & 15;

    float acc[8][8];
#pragma unroll
    for (int i = 0; i < 8; i++)
#pragma unroll
        for (int j = 0; j < 8; j++) acc[i][j] = 0.f;

    const float* Arow = A + (size_t)(row0 + lm) * K;
    const float* Brow = B + (size_t)(col0 + lm) * K;

    for (int kk = kbase; kk < kend; kk += 8) {
        int ka = kk + lk4;
        float4 av, bv;
        if (ka + 3 < kend) {
            av = *reinterpret_cast<const float4*>(Arow + ka);
            bv = *reinterpret_cast<const float4*>(Brow + ka);
        } else {
            float ta[4] = {0.f, 0.f, 0.f, 0.f}, tb[4] = {0.f, 0.f, 0.f, 0.f};
#pragma unroll
            for (int j = 0; j < 4; j++)
                if (ka + j < kend) { ta[j] = Arow[ka + j]; tb[j] = Brow[ka + j]; }
            av = make_float4(ta[0], ta[1], ta[2], ta[3]);
            bv = make_float4(tb[0], tb[1], tb[2], tb[3]);
        }
        As[lk4 + 0][lm] = av.x; As[lk4 + 1][lm] = av.y;
        As[lk4 + 2][lm] = av.z; As[lk4 + 3][lm] = av.w;
        Bs[lk4 + 0][lm] = bv.x; Bs[lk4 + 1][lm] = bv.y;
        Bs[lk4 + 2][lm] = bv.z; Bs[lk4 + 3][lm] = bv.w;
        __syncthreads();
#pragma unroll
        for (int k = 0; k < 8; k++) {
            const float4 a0 = *reinterpret_cast<const float4*>(&As[k][ty * 8]);
            const float4 a1 = *reinterpret_cast<const float4*>(&As[k][ty * 8 + 4]);
            const float4 b0 = *reinterpret_cast<const float4*>(&Bs[k][tx * 8]);
            const float4 b1 = *reinterpret_cast<const float4*>(&Bs[k][tx * 8 + 4]);
            float a[8] = {a0.x, a0.y, a0.z, a0.w, a1.x, a1.y, a1.z, a1.w};
            float b[8] = {b0.x, b0.y, b0.z, b0.w, b1.x, b1.y, b1.z, b1.w};
#pragma unroll
            for (int i = 0; i < 8; i++)
#pragma unroll
                for (int j = 0; j < 8; j++) acc[i][j] = fmaf(a[i], b[j], acc[i][j]);
        }
        __syncthreads();
    }

    const int crow = row0 + ty * 8;
    const int ccol = col0 + tx * 8;
#pragma unroll
    for (int i = 0; i < 8; i++) {
        float* Cp = C + (size_t)(crow + i) * N + ccol;
        float4 o0 = make_float4(acc[i][0], acc[i][1], acc[i][2], acc[i][3]);
        float4 o1 = make_float4(acc[i][4], acc[i][5], acc[i][6], acc[i][7]);
        *reinterpret_cast<float4*>(Cp)     = o0;
        *reinterpret_cast<float4*>(Cp + 4) = o1;
    }
}

// ====================== split-K reduce =======================================
__global__ void reduce_k(const float* __restrict__ part, float* __restrict__ dst,
                         int z, size_t len)
{
    size_t i = (size_t)blockIdx.x * 256 + threadIdx.x;
    if (i >= len) return;
    float s = 0.f;
    for (int zz = 0; zz < z; zz++) s += part[(size_t)zz * len + i];
    dst[i] = s;
}

// ====================== BatchNorm statistics (deterministic, 2-stage) ========
__global__ void bn_partial(const float* __restrict__ X1,
                           float* __restrict__ psum, float* __restrict__ psq)
{
    int ch = threadIdx.x;
    if (ch >= CC2) return;
    int b = blockIdx.x;
    const float* base = X1 + (size_t)b * 256 * CC2 + ch;
    float s = 0.f, q = 0.f;
    for (int r = 0; r < 256; r++) {
        float v = base[(size_t)r * CC2];
        s += v; q += v * v;
    }
    psum[b * CC2 + ch] = s;
    psq[b * CC2 + ch]  = q;
}

__global__ void bn_final(const float* __restrict__ psum, const float* __restrict__ psq,
                         const float* __restrict__ bns, const float* __restrict__ bnb,
                         float* __restrict__ scl, float* __restrict__ shf)
{
    int ch = threadIdx.x;
    if (ch >= CC2) return;
    float s = 0.f, q = 0.f;
    for (int b = 0; b < 256; b++) { s += psum[b * CC2 + ch]; q += psq[b * CC2 + ch]; }
    float mean = s * (1.f / MROWS);
    float var  = q * (1.f / MROWS) - mean * mean;
    float sc = bns[ch] / sqrtf(var + 1e-5f);
    scl[ch] = sc;
    shf[ch] = bnb[ch] - mean * sc;
}

// ====================== window gather (with roll -ws/2) + fused BN ===========
// Q[n, d], V[n, d]: n = (b, hh, ww), d = (dh, dw, cc); src row = (hh*ws+dh+sh)&127
__global__ void gather_qv(const float* __restrict__ X1,
                          const float* __restrict__ scl, const float* __restrict__ shf,
                          float* __restrict__ Q, float* __restrict__ V,
                          int gbase, int lws, int total)
{
    int idx = blockIdx.x * 256 + threadIdx.x;
    if (idx >= total) return;
    const int ws = 1 << lws;
    const int sh = ws >> 1;
    const int D  = (ws * ws) * 60;
    int n = idx / D;
    int d = idx - n * D;
    int cc = d % 60;
    int t  = d / 60;
    int dw = t & (ws - 1);
    int dh = t >> lws;
    const int lh = 7 - lws;                 // log2(128/ws)
    int b   = n >> (2 * lh);
    int rem = n & ((1 << (2 * lh)) - 1);
    int hh  = rem >> lh;
    int ww  = rem & ((1 << lh) - 1);
    int r = ((hh << lws) + dh + sh) & 127;
    int s = ((ww << lws) + dw + sh) & 127;
    size_t m = ((size_t)b << 14) + ((size_t)r << 7) + s;
    size_t base = m * CC2 + gbase + cc;
    int chq = gbase + cc, chv = chq + 60;
    Q[idx] = X1[base]      * scl[chq] + shf[chq];
    V[idx] = X1[base + 60] * scl[chv] + shf[chv];
}

// ====================== window scatter (inverse roll +ws/2) ==================
__global__ void scatter_y(const float* __restrict__ Yw, float* __restrict__ Ycat,
                          int g, int lws)
{
    int idx = blockIdx.x * 256 + threadIdx.x;     // over MROWS*60
    if (idx >= MROWS * 60) return;
    int cc = idx % 60;
    int m  = idx / 60;
    int so = m & 127, ro = (m >> 7) & 127, b = m >> 14;
    const int ws = 1 << lws, sh = ws >> 1, lh = 7 - lws;
    int r = (ro - sh) & 127, s = (so - sh) & 127;
    int hh = r >> lws, dh = r & (ws - 1);
    int ww = s >> lws, dw = s & (ws - 1);
    int n = (((b << lh) + hh) << lh) + ww;
    int D = (ws * ws) * 60;
    int d = ((dh << lws) + dw) * 60 + cc;
    Ycat[(size_t)m * CIN + g * 60 + cc] = Yw[(size_t)n * D + d];
}

// ====================== in-place row softmax =================================
__global__ __launch_bounds__(256) void softmax_rows(float* __restrict__ data, int N)
{
    __shared__ float sb[4096];
    __shared__ float red[40];
    const int tid = threadIdx.x;
    float* p = data + (size_t)blockIdx.x * N;

    float mx = -3.402823466e+38f;
    for (int i = tid; i < N; i += 256) { float v = p[i]; sb[i] = v; mx = fmaxf(mx, v); }
#pragma unroll
    for (int o = 16; o > 0; o >>= 1) mx = fmaxf(mx, __shfl_xor_sync(0xffffffffu, mx, o));
    if ((tid & 31) == 0) red[tid >> 5] = mx;
    __syncthreads();
    if (tid == 0) {
        float m2 = red[0];
        for (int i = 1; i < 8; i++) m2 = fmaxf(m2, red[i]);
        red[32] = m2;
    }
    __syncthreads();
    const float mAll = red[32];

    float sum = 0.f;
    for (int i = tid; i < N; i += 256) { float e = expf(sb[i] - mAll); sb[i] = e; sum += e; }
#pragma unroll
    for (int o = 16; o > 0; o >>= 1) sum += __shfl_xor_sync(0xffffffffu, sum, o);
    __syncthreads();
    if ((tid & 31) == 0) red[tid >> 5] = sum;
    __syncthreads();
    if (tid == 0) {
        float s2 = 0.f;
        for (int i = 0; i < 8; i++) s2 += red[i];
        red[33] = 1.f / s2;
    }
    __syncthreads();
    const float inv = red[33];
    for (int i = tid; i < N; i += 256) p[i] = sb[i] * inv;
}

// ====================== host orchestration ===================================
extern "C" void kernel_launch(void* const* d_in, const int* in_sizes, int n_in,
                              void* d_out, int out_size)
{
    const float* in  = (const float*)d_in[0];
    const float* w1  = (const float*)d_in[1];
    const float* b1  = (const float*)d_in[2];
    const float* bns = (const float*)d_in[3];
    const float* bnb = (const float*)d_in[4];
    const float* w2  = (const float*)d_in[5];
    const float* b2  = (const float*)d_in[6];
    float* out = (float*)d_out;

    float *X1, *Q, *V, *Yw, *Yc, *part, *psum, *psq, *scl, *shf;
    cudaGetSymbolAddress((void**)&X1,   g_X1);
    cudaGetSymbolAddress((void**)&Q,    g_Q);
    cudaGetSymbolAddress((void**)&V,    g_V);
    cudaGetSymbolAddress((void**)&Yw,   g_Yw);
    cudaGetSymbolAddress((void**)&Yc,   g_Ycat);
    cudaGetSymbolAddress((void**)&part, g_part);
    cudaGetSymbolAddress((void**)&psum, g_psum);
    cudaGetSymbolAddress((void**)&psq,  g_psq);
    cudaGetSymbolAddress((void**)&scl,  g_scale);
    cudaGetSymbolAddress((void**)&shf,  g_shift);

    // 1) conv1: X1 = in @ W1 + b1   (65536 x 360, K=180)
    gemm_nn<<<dim3((CC2 + 127) / 128, MROWS / 128), 256>>>(in, w1, X1, MROWS, CC2, CIN, b1);

    // 2) BatchNorm statistics (deterministic two-stage reduction)
    bn_partial<<<256, 384>>>(X1, psum, psq);
    bn_final<<<1, 384>>>(psum, psq, bns, bnb, scl, shf);

    // attention output regions inside d_out: [y | a4 | a8 | a16]
    float* attn[3] = { out + 11796480, out + 28573696, out + 29622272 };
    const int wsv[3]  = {4, 8, 16};
    const int lwsv[3] = {2, 3, 4};

    for (int g = 0; g < 3; g++) {
        const int ws  = wsv[g];
        const int lws = lwsv[g];
        const int Nw  = 4 * (128 / ws) * (128 / ws);   // windows: 4096 / 1024 / 256
        const int D   = ws * ws * 60;                   // 960 / 3840 / 15360

        // 3) gather Q,V with fused BN affine + roll(-ws/2)
        gather_qv<<<(NDTOT + 255) / 256, 256>>>(X1, scl, shf, Q, V, g * 120, lws, NDTOT);

        // 4) logits S = Q @ Q^T  (directly into d_out; split-K on small grids)
        if (g == 0) {
            gemm_nt<<<dim3(32, 32, 1), 256>>>(Q, Q, attn[0], 4096, 4096, 960, 960);
        } else if (g == 1) {
            gemm_nt<<<dim3(8, 8, 4), 256>>>(Q, Q, part, 1024, 1024, 3840, 960);
            reduce_k<<<4096, 256>>>(part, attn[1], 4, (size_t)1024 * 1024);
        } else {
            gemm_nt<<<dim3(2, 2, 60), 256>>>(Q, Q, part, 256, 256, 15360, 256);
            reduce_k<<<256, 256>>>(part, attn[2], 60, (size_t)256 * 256);
        }

        // 5) row-wise softmax, in place in d_out (these ARE the attn outputs)
        softmax_rows<<<Nw, 256>>>(attn[g], Nw);

        // 6) Yw = attn @ V   (M=Nw, N=D, K=Nw)
        gemm_nn<<<dim3((D + 127) / 128, Nw / 128), 256>>>(attn[g], V, Yw, Nw, D, Nw, nullptr);

        // 7) scatter back to image layout with roll(+ws/2), channel slice g*60
        scatter_y<<<(MROWS * 60 + 255) / 256, 256>>>(Yw, Yc, g, lws);
    }

    // 8) conv2: y = Ycat @ W2 + b2  -> front of d_out
    gemm_nn<<<dim3((CIN + 127) / 128, MROWS / 128), 256>>>(Yc, w2, out, MROWS, CIN, CIN, b2);
}